// round 3
// baseline (speedup 1.0000x reference)
#include <cuda_runtime.h>
#include <cstdint>

#define N_USERS    50000
#define N_ENTITIES 150000
#define N_NODES    200000
#define N_EDGES    3200000
#define BATCH      4096

typedef unsigned long long ull;

// ---------------- scratch (device globals; no allocation allowed) ----------
__device__ __align__(16) float g_h1[(size_t)N_NODES * 64];
__device__ __align__(16) float g_h2[(size_t)N_NODES * 32];
__device__ __align__(16) int   g_count[N_NODES];
__device__ __align__(16) int   g_rowstart[N_NODES + 1];
__device__ __align__(16) int   g_cursor[N_NODES];
__device__ __align__(16) int2  g_srt[N_EDGES];      // {neighbor, value-bits} sorted by target

__device__ __forceinline__ const float* feat0_row(const float* uw, const float* ew, int n) {
    return (n < N_USERS) ? (uw + (size_t)n * 64) : (ew + (size_t)(n - N_USERS) * 64);
}

__device__ __forceinline__ void ffma2(ull& d, ull a, ull b) {
    asm("fma.rn.f32x2 %0, %1, %2, %0;" : "+l"(d) : "l"(a), "l"(b));
}

// ---------------- CSR build ------------------------------------------------
__global__ void __launch_bounds__(256) k_zero_counts() {
    int i = blockIdx.x * 256 + threadIdx.x;           // int4 index
    if (i < N_NODES / 4) ((int4*)g_count)[i] = make_int4(0, 0, 0, 0);
}

__global__ void __launch_bounds__(256) k_count(const int* __restrict__ target) {
    int e = blockIdx.x * 256 + threadIdx.x;           // grid exact: 3.2M/256
    atomicAdd(&g_count[target[e]], 1);                // RED.ADD, no return
}

__global__ void __launch_bounds__(1024) k_scan() {
    const int CH = (N_NODES + 1023) / 1024;           // 196
    __shared__ int sa[1024], sb[1024];
    int t = threadIdx.x;
    int beg = t * CH;
    int end = beg + CH; if (end > N_NODES) end = N_NODES;
    int sum = 0;
    for (int i = beg; i < end; i++) sum += g_count[i];
    sa[t] = sum;
    __syncthreads();
    int* src = sa; int* dst = sb;
    for (int off = 1; off < 1024; off <<= 1) {
        dst[t] = (t >= off) ? src[t] + src[t - off] : src[t];
        __syncthreads();
        int* tmp = src; src = dst; dst = tmp;
    }
    int run = (t > 0) ? src[t - 1] : 0;               // exclusive prefix
    for (int i = beg; i < end; i++) {
        g_rowstart[i] = run;
        g_cursor[i]   = run;
        run += g_count[i];
    }
    if (t == 0) g_rowstart[N_NODES] = N_EDGES;
}

__global__ void __launch_bounds__(256) k_scatter(const int* __restrict__ target,
                                                const int* __restrict__ neighbor,
                                                const float* __restrict__ values) {
    int e = blockIdx.x * 256 + threadIdx.x;           // grid exact
    int t = target[e];
    int pos = atomicAdd(&g_cursor[t], 1);
    g_srt[pos] = make_int2(neighbor[e], __float_as_int(values[e]));
}

// ---------------- fused layer: gather + dense GEMM + lrelu + l2norm --------
// Per block: TM nodes. Phase 1 (gather): one warp per node (round-robin),
// CSR neighbor sum -> s = f+g, p = f*g written straight into shared A.
// Phase 2 (GEMM): out = lrelu([s|p] @ [W1;W2] + b1+b2), row-l2norm, store.
// A layout: As2[m][kp], kp = 0..63 (s pairs 0..31, p pairs 32..63), row
// padded to 65 float2 (520B) so a-loads at fixed kp hit distinct banks.
template <int LAYER>
__global__ void __launch_bounds__(256) k_fused(const float* __restrict__ uw,
                                               const float* __restrict__ ew,
                                               const float* __restrict__ W1,
                                               const float* __restrict__ b1,
                                               const float* __restrict__ W2,
                                               const float* __restrict__ b2) {
    constexpr int NOUT = (LAYER == 1) ? 64 : 32;
    constexpr int CQ   = NOUT / 4;          // 16 / 8
    constexpr int TM   = (256 / CQ) * 4;    // 64 / 128
    constexpr int APITCH = 65;              // float2 per A row (pad)

    extern __shared__ __align__(16) char smem_raw[];
    float2* As2 = (float2*)smem_raw;                            // [TM][APITCH]
    float2* Bs2 = (float2*)(smem_raw + TM * APITCH * sizeof(float2)); // [64][NOUT]

    int tid  = threadIdx.x;
    int warp = tid >> 5;
    int lane = tid & 31;
    int blockBase = blockIdx.x * TM;

    // ---- stage B: all 64 k-pairs of [W1;W2] -------------------------------
    for (int idx = tid; idx < 64 * NOUT; idx += 256) {
        int kp = idx / NOUT;
        int j  = idx % NOUT;
        int kg = kp * 2;
        float w0, w1;
        if (kg < 64) { w0 = W1[kg * NOUT + j];        w1 = W1[(kg + 1) * NOUT + j]; }
        else         { w0 = W2[(kg - 64) * NOUT + j]; w1 = W2[(kg - 63) * NOUT + j]; }
        Bs2[kp * NOUT + j] = make_float2(w0, w1);
    }

    // ---- gather phase: warp per node, 16 lanes x float4, 2 edges in flight
    {
        int c = lane & 15, half = lane >> 4;
        for (int w = warp; w < TM; w += 8) {
            int node = blockBase + w;
            if (node < N_NODES) {
                const float* fr = (LAYER == 1) ? feat0_row(uw, ew, node)
                                               : (g_h1 + (size_t)node * 64);
                float4 f = *(const float4*)(fr + c * 4);
                int base = g_rowstart[node];
                int end  = g_rowstart[node + 1];
                float4 acc = make_float4(0.f, 0.f, 0.f, 0.f);
                for (int i = base + half; i < end; i += 2) {
                    int2 e = g_srt[i];
                    float v = __int_as_float(e.y);
                    const float* src = (LAYER == 1) ? feat0_row(uw, ew, e.x)
                                                    : (g_h1 + (size_t)e.x * 64);
                    float4 nf = *(const float4*)(src + c * 4);
                    acc.x = fmaf(nf.x, v, acc.x);
                    acc.y = fmaf(nf.y, v, acc.y);
                    acc.z = fmaf(nf.z, v, acc.z);
                    acc.w = fmaf(nf.w, v, acc.w);
                }
                acc.x += __shfl_xor_sync(0xffffffffu, acc.x, 16);
                acc.y += __shfl_xor_sync(0xffffffffu, acc.y, 16);
                acc.z += __shfl_xor_sync(0xffffffffu, acc.z, 16);
                acc.w += __shfl_xor_sync(0xffffffffu, acc.w, 16);
                if (half == 0) {
                    float2* row = As2 + w * APITCH;
                    row[2 * c]          = make_float2(f.x + acc.x, f.y + acc.y);
                    row[2 * c + 1]      = make_float2(f.z + acc.z, f.w + acc.w);
                    row[32 + 2 * c]     = make_float2(f.x * acc.x, f.y * acc.y);
                    row[32 + 2 * c + 1] = make_float2(f.z * acc.z, f.w * acc.w);
                }
            } else if (half == 0) {
                float2* row = As2 + w * APITCH;
                row[2 * c] = row[2 * c + 1] = make_float2(0.f, 0.f);
                row[32 + 2 * c] = row[32 + 2 * c + 1] = make_float2(0.f, 0.f);
            }
        }
    }

    // bias per thread column
    int r = tid / CQ;       // node quad
    int c = tid % CQ;       // col within group
    float bsum[4];
    #pragma unroll
    for (int jj = 0; jj < 4; jj++) {
        int j = c + jj * CQ;
        bsum[jj] = b1[j] + b2[j];
    }

    __syncthreads();

    // ---- GEMM mainloop: 64 k-pairs ---------------------------------------
    ull acc[4][4];
    #pragma unroll
    for (int i = 0; i < 4; i++)
        #pragma unroll
        for (int jj = 0; jj < 4; jj++) acc[i][jj] = 0ull;

    #pragma unroll 8
    for (int kp = 0; kp < 64; kp++) {
        ull a[4], b[4];
        #pragma unroll
        for (int i = 0; i < 4; i++)  a[i]  = *(const ull*)&As2[(r * 4 + i) * APITCH + kp];
        #pragma unroll
        for (int jj = 0; jj < 4; jj++) b[jj] = *(const ull*)&Bs2[kp * NOUT + c + jj * CQ];
        #pragma unroll
        for (int i = 0; i < 4; i++)
            #pragma unroll
            for (int jj = 0; jj < 4; jj++)
                ffma2(acc[i][jj], a[i], b[jj]);
    }

    // ---- epilogue: bias, leaky relu, row l2-norm, store -------------------
    float* OUT = (LAYER == 1) ? g_h1 : g_h2;
    #pragma unroll
    for (int i = 0; i < 4; i++) {
        int node = blockBase + r * 4 + i;
        float v[4];
        float sq = 0.f;
        #pragma unroll
        for (int jj = 0; jj < 4; jj++) {
            ull x = acc[i][jj];
            float lo = __uint_as_float((unsigned)(x & 0xffffffffull));
            float hi = __uint_as_float((unsigned)(x >> 32));
            float s = lo + hi + bsum[jj];
            s = (s >= 0.f) ? s : 0.01f * s;
            v[jj] = s;
            sq = fmaf(s, s, sq);
        }
        #pragma unroll
        for (int off = CQ / 2; off > 0; off >>= 1)
            sq += __shfl_xor_sync(0xffffffffu, sq, off);
        float inv = 1.f / fmaxf(sqrtf(sq), 1e-12f);
        if (node < N_NODES) {
            #pragma unroll
            for (int jj = 0; jj < 4; jj++)
                OUT[(size_t)node * NOUT + c + jj * CQ] = v[jj] * inv;
        }
    }
}

// ---------------- scoring: one warp per batch element ----------------------
__global__ void __launch_bounds__(256) k_score(const float* __restrict__ uw,
                                               const float* __restrict__ ew,
                                               const int* __restrict__ uid,
                                               const int* __restrict__ pid,
                                               const int* __restrict__ nid,
                                               float* __restrict__ out) {
    int gidx = blockIdx.x * 256 + threadIdx.x;
    int b = gidx >> 5;
    int l = gidx & 31;
    if (b >= BATCH) return;
    int u  = uid[b];
    int pe = pid[b];
    int ne = nid[b];
    int p  = N_USERS + pe;
    int q  = N_USERS + ne;

    const float* fu = uw + (size_t)u * 64;
    const float* fp = ew + (size_t)pe * 64;
    const float* fq = ew + (size_t)ne * 64;

    float sp = 0.f, sn = 0.f;
    #pragma unroll
    for (int r = 0; r < 2; r++) {
        int cidx = l + r * 32;
        float a = fu[cidx];
        sp = fmaf(a, fp[cidx], sp);
        sn = fmaf(a, fq[cidx], sn);
    }
    #pragma unroll
    for (int r = 0; r < 2; r++) {
        int cidx = l + r * 32;
        float a = g_h1[(size_t)u * 64 + cidx];
        sp = fmaf(a, g_h1[(size_t)p * 64 + cidx], sp);
        sn = fmaf(a, g_h1[(size_t)q * 64 + cidx], sn);
    }
    {
        float a = g_h2[(size_t)u * 32 + l];
        sp = fmaf(a, g_h2[(size_t)p * 32 + l], sp);
        sn = fmaf(a, g_h2[(size_t)q * 32 + l], sn);
    }
    #pragma unroll
    for (int o = 16; o > 0; o >>= 1) {
        sp += __shfl_xor_sync(0xffffffffu, sp, o);
        sn += __shfl_xor_sync(0xffffffffu, sn, o);
    }
    if (l == 0) { out[b] = sp; out[BATCH + b] = sn; }
}

// ---------------- launch ---------------------------------------------------
extern "C" void kernel_launch(void* const* d_in, const int* in_sizes, int n_in,
                              void* d_out, int out_size) {
    const float* uw   = (const float*)d_in[0];
    const float* ew   = (const float*)d_in[1];
    const float* W1a  = (const float*)d_in[2];
    const float* b1a  = (const float*)d_in[3];
    const float* W2a  = (const float*)d_in[4];
    const float* b2a  = (const float*)d_in[5];
    const float* W1b  = (const float*)d_in[6];
    const float* b1b  = (const float*)d_in[7];
    const float* W2b  = (const float*)d_in[8];
    const float* b2b  = (const float*)d_in[9];
    const float* values   = (const float*)d_in[10];
    const int*   target   = (const int*)d_in[11];
    const int*   neighbor = (const int*)d_in[12];
    const int*   uid      = (const int*)d_in[13];
    const int*   pid      = (const int*)d_in[14];
    const int*   nid      = (const int*)d_in[15];
    float* out = (float*)d_out;

    // Dynamic smem sizes: L1 = 64*65*8 + 64*64*8, L2 = 128*65*8 + 64*32*8
    const int SMEM1 = 64 * 65 * 8 + 64 * 64 * 8;    // 66048
    const int SMEM2 = 128 * 65 * 8 + 64 * 32 * 8;   // 82944
    cudaFuncSetAttribute(k_fused<1>, cudaFuncAttributeMaxDynamicSharedMemorySize, SMEM1);
    cudaFuncSetAttribute(k_fused<2>, cudaFuncAttributeMaxDynamicSharedMemorySize, SMEM2);

    // CSR build (once; reused by both layers)
    k_zero_counts<<<(N_NODES / 4 + 255) / 256, 256>>>();
    k_count<<<N_EDGES / 256, 256>>>(target);
    k_scan<<<1, 1024>>>();
    k_scatter<<<N_EDGES / 256, 256>>>(target, neighbor, values);

    // Layer 1 (fused gather + dense): grid exact 200000/64
    k_fused<1><<<N_NODES / 64, 256, SMEM1>>>(uw, ew, W1a, b1a, W2a, b2a);

    // Layer 2: ceil(200000/128)
    k_fused<2><<<(N_NODES + 127) / 128, 256, SMEM2>>>(uw, ew, W1b, b1b, W2b, b2b);

    // Scores
    k_score<<<(BATCH * 32) / 256, 256>>>(uw, ew, uid, pid, nid, out);
}